// round 10
// baseline (speedup 1.0000x reference)
#include <cuda_runtime.h>

#define NCLS  19
#define DIM   256
#define NPIX  4096
#define NBINS 51
#define NW    (NCLS * DIM)    // 4864 tasks; 1 per warp
#define NBLK  (NW / 4)        // 1216 blocks x 4 warps
#define VCAP  512             // per-warp value buffer (cnt ~215 +- 14, safe)

// ---- scratch (no allocations allowed) ----
__device__ int   g_off[NCLS + 1];
__device__ int   g_cnt[NCLS];
__device__ float g_Fs[DIM * NPIX];          // class-sorted values, d-major
__device__ float g_miu[DIM * NCLS];         // [d][c]
__device__ float g_var[DIM * NCLS];
__device__ float g_clsum2[NCLS * 32];       // spread class partial sums
__device__ int   g_ticket;

__device__ __forceinline__ float wredsum(float v) {
#pragma unroll
    for (int m = 16; m; m >>= 1) v += __shfl_xor_sync(0xffffffffu, v, m);
    return v;
}

__device__ __forceinline__ int wrscan_incl(int v, int lane) {
#pragma unroll
    for (int o = 1; o < 32; o <<= 1) {
        int t = __shfl_up_sync(0xffffffffu, v, o);
        if (lane >= o) v += t;
    }
    return v;
}

__device__ __forceinline__ float ex2(float x) {
    float e;
    asm("ex2.approx.ftz.f32 %0, %1;" : "=f"(e) : "f"(x));
    return e;
}

// K0: per-d gather with block-local counting sort + per-(c,d) stats.
__global__ void __launch_bounds__(256) k_gp(const int* __restrict__ lab32,
                                            const float* __restrict__ feature) {
    __shared__ short sperm[NPIX];          // 8KB
    __shared__ int scnt[8][20];            // [warp][class] -> excl prefix
    __shared__ int stot[20];
    __shared__ int soff[20];
    int tid  = threadIdx.x;
    int w    = tid >> 5;
    int lane = tid & 31;

    // words [0,4096): in-bounds under both dtype views of the label buffer.
    int aw[16];
#pragma unroll
    for (int r = 0; r < 16; r++) aw[r] = lab32[tid + r * 256];
    // int64 labels (0..18): all odd words zero; odd words owned by odd tid.
    int any = 0;
    if (tid & 1) {
#pragma unroll
        for (int r = 0; r < 16; r++) any |= aw[r];
    }
    int is32 = __syncthreads_or(any);

    if (lane < 20) scnt[w][lane] = 0;
    __syncwarp();

    int cs[16], rs[16];
#pragma unroll
    for (int r = 0; r < 16; r++) {
        int n = tid + r * 256;
        int c = is32 ? aw[r] : lab32[2 * n];
        c = max(0, min(NCLS - 1, c));
        cs[r] = c;
        unsigned mask = __match_any_sync(0xffffffffu, c);
        int base = scnt[w][c];
        rs[r] = base + __popc(mask & ((1u << lane) - 1u));
        if (lane == (__ffs(mask) - 1)) scnt[w][c] = base + __popc(mask);
        __syncwarp();
    }
    __syncthreads();

    if (tid < NCLS) {
        int run = 0;
#pragma unroll
        for (int w2 = 0; w2 < 8; w2++) {
            int t = scnt[w2][tid];
            scnt[w2][tid] = run;
            run += t;
        }
        stot[tid] = run;
    }
    __syncthreads();
    if (tid == 0) {
        int off = 0;
        for (int c = 0; c < NCLS; c++) { soff[c] = off; off += stot[c]; }
    }
    __syncthreads();

#pragma unroll
    for (int r = 0; r < 16; r++) {
        int c = cs[r];
        sperm[soff[c] + scnt[w][c] + rs[r]] = (short)(tid + r * 256);
    }

    if (blockIdx.x == 0) {
        if (tid < NCLS) { g_cnt[tid] = stot[tid]; g_off[tid] = soff[tid]; }
        if (tid == NCLS) g_off[NCLS] = NPIX;
        for (int i = tid; i < NCLS * 32; i += 256) g_clsum2[i] = 0.f;
        if (tid == 255) g_ticket = 0;
    }
    __syncthreads();

    int d = blockIdx.x;
    const float* __restrict__ src = feature + d * NPIX;
    float* __restrict__ dst = g_Fs + d * NPIX;
    for (int j = tid; j < NPIX; j += 256)
        dst[j] = src[sperm[j]];
    __syncthreads();

    // stats: warp w reduces classes w, w+8, w+16 (dst row is L1-hot)
    for (int c = w; c < NCLS; c += 8) {
        int off = soff[c];
        int cnt = stot[c];
        float s1 = 0.f, s2 = 0.f;
        for (int i = lane; i < cnt; i += 32) {
            float f = dst[off + i];
            s1 += f;
            s2 = fmaf(f, f, s2);
        }
        s1 = wredsum(s1);
        s2 = wredsum(s2);
        if (lane == 0 && cnt > 0) {
            float cm  = (float)cnt;
            float miu = s1 / cm;
            g_miu[d * NCLS + c] = miu;
            g_var[d * NCLS + c] = fmaxf(s2 / cm - miu * miu, 1e-12f);
        }
    }
}

// K1: windowed KDE. One warp per (c,d). Bucket-count-sort values by nearest
// bin (smem), then lane L owns bins L and L+32 and sums only the bucket
// window [k-W, k+W] (truncation below 2^-34 -> negligible).
__global__ void __launch_bounds__(128, 9)
k_main(const float* __restrict__ feature, float* __restrict__ out, int nf) {
    __shared__ float sval[4][VCAP];
    __shared__ int   sbase[4][52];
    __shared__ int   scur[4][52];
    __shared__ float sh[4][52];
    int wslot = threadIdx.x >> 5;
    int wtask = blockIdx.x * 4 + wslot;   // 0..4863
    int lane = threadIdx.x & 31;
    int c = wtask >> 8;
    int d = wtask & 255;
    int off = g_off[c];
    int cnt = g_off[c + 1] - off;
    const float LOG2E = 1.4426950408889634f;

    if (cnt > 0) {
        const float* __restrict__ fp = g_Fs + d * NPIX + off;
        float miu = g_miu[d * NCLS + c];
        float var = g_var[d * NCLS + c];
        // vs = var/25 ; base-2 coef: a_s = -12.5*log2e/var
        float a_s = -12.5f * LOG2E / var;

        float sv0 = 0.f, sv1 = 0.f;
        int k0 = lane, k1 = lane + 32;

        if (cnt <= VCAP) {
            // window radius in buckets: drop terms with exponent < -34
            float w = sqrtf(34.f / (-a_s));
            int W = (int)ceilf((w + 0.1f) * 5.f);
            if (W > 51) W = 51;

            int* cntw  = scur[wslot];     // counts first, cursors later
            int* basew = sbase[wslot];
            float* vw  = sval[wslot];

            if (lane < 26) { cntw[lane] = 0; cntw[lane + 26] = 0; }
            __syncwarp();
            for (int i = lane; i < cnt; i += 32) {
                float f = fp[i];
                int b = (int)floorf(fmaf(f, 5.f, 25.5f));
                b = max(0, min(50, b));
                atomicAdd(&cntw[b], 1);
            }
            __syncwarp();
            // exclusive prefix over 51 buckets -> basew[0..51]
            int x0 = cntw[lane];
            int x1 = (lane < 19) ? cntw[32 + lane] : 0;
            int in0 = wrscan_incl(x0, lane);
            int in1 = wrscan_incl(x1, lane);
            int tot0 = __shfl_sync(0xffffffffu, in0, 31);
            int tot1 = __shfl_sync(0xffffffffu, in1, 18);
            basew[lane] = in0 - x0;
            if (lane < 19) basew[32 + lane] = tot0 + in1 - x1;
            if (lane == 0) basew[51] = tot0 + tot1;
            __syncwarp();
            // cursors = copy of bases
            cntw[lane] = basew[lane];
            if (lane < 19) cntw[32 + lane] = basew[32 + lane];
            __syncwarp();
            // scatter values in bucket order
            for (int i = lane; i < cnt; i += 32) {
                float f = fp[i];
                int b = (int)floorf(fmaf(f, 5.f, 25.5f));
                b = max(0, min(50, b));
                int p = atomicAdd(&cntw[b], 1);
                vw[p] = f;
            }
            __syncwarp();

            // lane-owned windowed accumulation
            {
                int lo = basew[max(0, k0 - W)];
                int hi = basew[min(51, k0 + W + 1)];
                float bk = fmaf(0.2f, (float)k0, -5.f);
#pragma unroll 2
                for (int i = lo; i < hi; i++) {
                    float t = vw[i] - bk;
                    sv0 += ex2((a_s * t) * t);
                }
            }
            if (k1 < NBINS) {
                int lo = basew[max(0, k1 - W)];
                int hi = basew[min(51, k1 + W + 1)];
                float bk = fmaf(0.2f, (float)k1, -5.f);
#pragma unroll 2
                for (int i = lo; i < hi; i++) {
                    float t = vw[i] - bk;
                    sv1 += ex2((a_s * t) * t);
                }
            }
        } else {
            // fallback (never hit for this dataset): full window from gmem
            float bk0 = fmaf(0.2f, (float)k0, -5.f);
            float bk1 = fmaf(0.2f, (float)k1, -5.f);
            for (int i = 0; i < cnt; i++) {
                float f = fp[i];
                float t0 = f - bk0;
                sv0 += ex2((a_s * t0) * t0);
                if (k1 < NBINS) {
                    float t1 = f - bk1;
                    sv1 += ex2((a_s * t1) * t1);
                }
            }
        }

        // epilogue: lane k owns bins k and k+32 (sv0/sv1 already per-lane)
        bool hi = k1 < NBINS;
        if (!hi) sv1 = 0.f;
        float sumS = wredsum(sv0 + sv1);

        float at = -0.5f * LOG2E / var;
        float b0 = fmaf(0.2f, (float)lane, -5.f);
        float b1 = b0 + 6.4f;
        float d0 = b0 - miu, d1 = b1 - miu;
        float g0 = ex2(at * d0 * d0);
        float g1 = hi ? ex2(at * d1 * d1) : 0.f;
        float sumT = wredsum(g0 + g1);

        float invS = 1.f / fmaxf(sumS, 1e-30f);
        float invT = 1.f / fmaxf(sumT, 1e-30f);

        float df0 = sv0 * invS - g0 * invT;
        float df1 = sv1 * invS - g1 * invT;
        float ad0 = fabsf(df0), ad1 = fabsf(df1);
        float l0 = (ad0 < 1.f) ? 0.5f * df0 * df0 : ad0 - 0.5f;
        float l1 = (ad1 < 1.f) ? 0.5f * df1 * df1 : ad1 - 0.5f;
        if (!hi) l1 = 0.f;

        float sl = wredsum(l0 + l1);
        if (lane == 0) atomicAdd(&g_clsum2[c * 32 + (d & 31)], sl);
        (void)sh;
    }

    // publish, ticket; the last of the NW warps finalizes.
    __threadfence();
    int tk = 0;
    if (lane == 0) tk = atomicAdd(&g_ticket, 1);
    tk = __shfl_sync(0xffffffffu, tk, 0);
    if (tk == NW - 1) {
        float v = 0.f, a = 0.f;
#pragma unroll
        for (int j = 1; j < NCLS; j++) {          // class 0 excluded
            int cj = __ldcg(&g_cnt[j]);
            float x = __ldcg(&g_clsum2[j * 32 + lane]);
            if (cj > 0) { v += x; a += (lane == 0) ? 1.f : 0.f; }
        }
        v = wredsum(v);
        a = wredsum(a);
        if (lane == 0) out[0] = (v * (1.f / 13056.f)) / (a + 1e-12f);
    }

    // output copy: out[1..nf] = feature[0..nf), overlapped across blocks
    int gt = blockIdx.x * 128 + threadIdx.x;
    for (int j = gt; j < nf; j += NBLK * 128)
        out[1 + j] = feature[j];
}

extern "C" void kernel_launch(void* const* d_in, const int* in_sizes, int n_in,
                              void* d_out, int out_size) {
    // Inputs: feature (1048576 f32) and label (4096 px); smaller buffer = label.
    int fi = 0, li = 1;
    if (n_in >= 2 && in_sizes[0] < in_sizes[1]) { fi = 1; li = 0; }
    const float* feature = (const float*)d_in[fi];
    const int*   label   = (const int*)d_in[li];
    float* out = (float*)d_out;

    int nf = out_size - 1;
    int cap = DIM * NPIX;
    if (nf > cap) nf = cap;
    if (nf < 0) nf = 0;

    k_gp<<<DIM, 256>>>(label, feature);
    k_main<<<NBLK, 128>>>(feature, out, nf);
}

// round 11
// speedup vs baseline: 1.4626x; 1.4626x over previous
#include <cuda_runtime.h>

#define NCLS  19
#define DIM   256
#define NPIX  4096
#define NBINS 51
#define NW    (NCLS * DIM)    // 4864 tasks
#define NBLK  1184            // 148 SMs x 8 blocks -> exactly 1 wave
#define TOTW  (NBLK * 4)      // 4736 resident warps pulling tasks

// ---- scratch (no allocations allowed) ----
__device__ int   g_off[NCLS + 1];
__device__ int   g_cnt[NCLS];
__device__ float g_Fs[DIM * NPIX];          // class-sorted values, d-major
__device__ float g_clsum2[NCLS * 32];       // spread class partial sums
__device__ int   g_ticket;
__device__ int   g_task;

__device__ __forceinline__ float wredsum(float v) {
#pragma unroll
    for (int m = 16; m; m >>= 1) v += __shfl_xor_sync(0xffffffffu, v, m);
    return v;
}

__device__ __forceinline__ float ex2(float x) {
    float e;
    asm("ex2.approx.ftz.f32 %0, %1;" : "=f"(e) : "f"(x));
    return e;
}

// KDE sub-pass, KB bins from BSTART, 2 pixels/lane/iter (2 indep EX2 chains).
template <int KB, int BSTART>
__device__ __forceinline__ void kde_pass(const float* __restrict__ vals, int cnt,
                                         int lane, float a_s, float* sh_out) {
    float acc[KB];
#pragma unroll
    for (int k = 0; k < KB; k++) acc[k] = 0.f;
    int cm1 = cnt - 1;
    for (int i = lane; i < cnt; i += 64) {
        int j  = i + 32;
        float fa = vals[i];
        float fb = vals[min(j, cm1)];
        if (j >= cnt) fb = 1e19f;           // pad -> exact 0 contribution
        float p1a = (-2.f * a_s) * fa, p0a = a_s * fa * fa;
        float p1b = (-2.f * a_s) * fb, p0b = a_s * fb * fb;
#pragma unroll
        for (int k = 0; k < KB; k++) {
            float bk  = -5.f + 0.2f * (float)(BSTART + k);
            float ea = ex2(fmaf(a_s, bk * bk, fmaf(p1a, bk, p0a)));
            float eb = ex2(fmaf(a_s, bk * bk, fmaf(p1b, bk, p0b)));
            acc[k] += ea + eb;
        }
    }
#pragma unroll
    for (int k = 0; k < KB; k++) {
        acc[k] = wredsum(acc[k]);
        if (lane == 0) sh_out[k] = acc[k];
    }
}

// K0: block handles dims d and d+128. Block-local counting sort (labels are
// 16KB, L2-broadcast) + gather into g_Fs. No stats (k_main pass 1 does them).
__global__ void __launch_bounds__(256) k_gp(const int* __restrict__ lab32,
                                            const float* __restrict__ feature) {
    __shared__ short sperm[NPIX];          // 8KB
    __shared__ int scnt[8][20];            // [warp][class] -> excl prefix
    __shared__ int stot[20];
    __shared__ int soff[20];
    int tid  = threadIdx.x;
    int w    = tid >> 5;
    int lane = tid & 31;

    // words [0,4096): in-bounds under both dtype views of the label buffer.
    int aw[16];
#pragma unroll
    for (int r = 0; r < 16; r++) aw[r] = lab32[tid + r * 256];
    // int64 labels (0..18): all odd words zero; odd words owned by odd tid.
    int any = 0;
    if (tid & 1) {
#pragma unroll
        for (int r = 0; r < 16; r++) any |= aw[r];
    }
    int is32 = __syncthreads_or(any);

    if (lane < 20) scnt[w][lane] = 0;
    __syncwarp();

    int cs[16], rs[16];
#pragma unroll
    for (int r = 0; r < 16; r++) {
        int n = tid + r * 256;
        int c = is32 ? aw[r] : lab32[2 * n];
        c = max(0, min(NCLS - 1, c));
        cs[r] = c;
        unsigned mask = __match_any_sync(0xffffffffu, c);
        int base = scnt[w][c];
        rs[r] = base + __popc(mask & ((1u << lane) - 1u));
        if (lane == (__ffs(mask) - 1)) scnt[w][c] = base + __popc(mask);
        __syncwarp();
    }
    __syncthreads();

    // cross-warp exclusive prefix per class
    if (tid < NCLS) {
        int run = 0;
#pragma unroll
        for (int w2 = 0; w2 < 8; w2++) {
            int t = scnt[w2][tid];
            scnt[w2][tid] = run;
            run += t;
        }
        stot[tid] = run;
    }
    __syncthreads();
    if (tid == 0) {
        int off = 0;
        for (int c = 0; c < NCLS; c++) { soff[c] = off; off += stot[c]; }
    }
    __syncthreads();

#pragma unroll
    for (int r = 0; r < 16; r++) {
        int c = cs[r];
        sperm[soff[c] + scnt[w][c] + rs[r]] = (short)(tid + r * 256);
    }

    if (blockIdx.x == 0) {
        if (tid < NCLS) { g_cnt[tid] = stot[tid]; g_off[tid] = soff[tid]; }
        if (tid == NCLS) g_off[NCLS] = NPIX;
        for (int i = tid; i < NCLS * 32; i += 256) g_clsum2[i] = 0.f;
        if (tid == 254) g_task = 0;
        if (tid == 255) g_ticket = 0;
    }
    __syncthreads();

#pragma unroll 1
    for (int dd = 0; dd < 2; dd++) {
        int d = blockIdx.x + dd * 128;
        const float* __restrict__ src = feature + d * NPIX;
        float* __restrict__ dst = g_Fs + d * NPIX;
        for (int j = tid; j < NPIX; j += 256)
            dst[j] = src[sperm[j]];
    }
}

// K1: persistent warps pull (c,d) tasks from a global counter (perfect SM
// load balance). Per task: stats pass (warms L1) + split 2px-ILP KDE +
// epilogue + spread atomic. Ticketed finalize; output copy tail.
__global__ void __launch_bounds__(128, 8)
k_main(const float* __restrict__ feature, float* __restrict__ out, int nf) {
    __shared__ float sh[4][52];
    int wslot = threadIdx.x >> 5;
    int lane = threadIdx.x & 31;
    const float LOG2E = 1.4426950408889634f;

    for (;;) {
        int t = 0;
        if (lane == 0) t = atomicAdd(&g_task, 1);
        t = __shfl_sync(0xffffffffu, t, 0);
        if (t >= NW) break;

        int c = t >> 8;
        int d = t & 255;
        int off = g_off[c];
        int cnt = g_off[c + 1] - off;
        if (cnt <= 0) continue;

        const float* __restrict__ fp = g_Fs + d * NPIX + off;

        // pass 1: mean/var (also warms L1 for the KDE passes)
        float s1 = 0.f, s2 = 0.f;
        for (int i = lane; i < cnt; i += 32) {
            float f = fp[i];
            s1 += f;
            s2 = fmaf(f, f, s2);
        }
        s1 = wredsum(s1);
        s2 = wredsum(s2);
        float cm  = (float)cnt;
        float miu = s1 / cm;
        float var = fmaxf(s2 / cm - miu * miu, 1e-12f);

        // vs = var/25 ; base-2 coef: -12.5*log2e/var
        float a_s = -12.5f * LOG2E / var;

        kde_pass<26, 0>(fp, cnt, lane, a_s, &sh[wslot][0]);
        kde_pass<25, 26>(fp, cnt, lane, a_s, &sh[wslot][26]);
        __syncwarp();

        // epilogue: lane k owns bins k and k+32
        bool hi = lane < (NBINS - 32);
        float sv0 = sh[wslot][lane];
        float sv1 = hi ? sh[wslot][lane + 32] : 0.f;
        float sumS = wredsum(sv0 + sv1);

        float at = -0.5f * LOG2E / var;
        float b0 = fmaf(0.2f, (float)lane, -5.f);
        float b1 = b0 + 6.4f;
        float d0 = b0 - miu, d1 = b1 - miu;
        float g0 = ex2(at * d0 * d0);
        float g1 = hi ? ex2(at * d1 * d1) : 0.f;
        float sumT = wredsum(g0 + g1);

        float invS = 1.f / fmaxf(sumS, 1e-30f);
        float invT = 1.f / fmaxf(sumT, 1e-30f);

        float df0 = sv0 * invS - g0 * invT;
        float df1 = sv1 * invS - g1 * invT;
        float ad0 = fabsf(df0), ad1 = fabsf(df1);
        float l0 = (ad0 < 1.f) ? 0.5f * df0 * df0 : ad0 - 0.5f;
        float l1 = (ad1 < 1.f) ? 0.5f * df1 * df1 : ad1 - 0.5f;
        if (!hi) l1 = 0.f;

        float sl = wredsum(l0 + l1);
        if (lane == 0) atomicAdd(&g_clsum2[c * 32 + (d & 31)], sl);
    }

    // publish, ticket; the last of the TOTW warps finalizes.
    __threadfence();
    int tk = 0;
    if (lane == 0) tk = atomicAdd(&g_ticket, 1);
    tk = __shfl_sync(0xffffffffu, tk, 0);
    if (tk == TOTW - 1) {
        float v = 0.f, a = 0.f;
#pragma unroll
        for (int j = 1; j < NCLS; j++) {          // class 0 excluded
            int cj = __ldcg(&g_cnt[j]);
            float x = __ldcg(&g_clsum2[j * 32 + lane]);
            if (cj > 0) { v += x; a += (lane == 0) ? 1.f : 0.f; }
        }
        v = wredsum(v);
        a = wredsum(a);
        if (lane == 0) out[0] = (v * (1.f / 13056.f)) / (a + 1e-12f);
    }

    // output copy: out[1..nf] = feature[0..nf), overlapped across blocks
    int gt = blockIdx.x * 128 + threadIdx.x;
    for (int j = gt; j < nf; j += NBLK * 128)
        out[1 + j] = feature[j];
}

extern "C" void kernel_launch(void* const* d_in, const int* in_sizes, int n_in,
                              void* d_out, int out_size) {
    // Inputs: feature (1048576 f32) and label (4096 px); smaller buffer = label.
    int fi = 0, li = 1;
    if (n_in >= 2 && in_sizes[0] < in_sizes[1]) { fi = 1; li = 0; }
    const float* feature = (const float*)d_in[fi];
    const int*   label   = (const int*)d_in[li];
    float* out = (float*)d_out;

    int nf = out_size - 1;
    int cap = DIM * NPIX;
    if (nf > cap) nf = cap;
    if (nf < 0) nf = 0;

    k_gp<<<128, 256>>>(label, feature);
    k_main<<<NBLK, 128>>>(feature, out, nf);
}

// round 12
// speedup vs baseline: 1.5653x; 1.0703x over previous
#include <cuda_runtime.h>

#define NCLS  19
#define DIM   256
#define NPIX  4096
#define NBINS 51
#define NW    (NCLS * DIM)    // 4864 tasks; 1 per warp
#define NBLK  (NW / 4)        // 1216 blocks x 4 warps; 9 blocks/SM

// ---- scratch (no allocations allowed) ----
__device__ int   g_off[NCLS + 1];
__device__ int   g_cnt[NCLS];
__device__ float g_Fs[DIM * NPIX];          // class-sorted values, d-major
__device__ float g_clsum2[NCLS * 32];       // spread class partial sums
__device__ int   g_ticket;

__device__ __forceinline__ float wredsum(float v) {
#pragma unroll
    for (int m = 16; m; m >>= 1) v += __shfl_xor_sync(0xffffffffu, v, m);
    return v;
}

__device__ __forceinline__ float ex2(float x) {
    float e;
    asm("ex2.approx.ftz.f32 %0, %1;" : "=f"(e) : "f"(x));
    return e;
}

// KDE sub-pass, KB bins from BSTART, 2 pixels/lane/iter (2 indep EX2 chains).
template <int KB, int BSTART>
__device__ __forceinline__ void kde_pass(const float* __restrict__ vals, int cnt,
                                         int lane, float a_s, float* sh_out) {
    float acc[KB];
#pragma unroll
    for (int k = 0; k < KB; k++) acc[k] = 0.f;
    int cm1 = cnt - 1;
    for (int i = lane; i < cnt; i += 64) {
        int j  = i + 32;
        float fa = vals[i];
        float fb = vals[min(j, cm1)];
        if (j >= cnt) fb = 1e19f;           // pad -> exact 0 contribution
        float p1a = (-2.f * a_s) * fa, p0a = a_s * fa * fa;
        float p1b = (-2.f * a_s) * fb, p0b = a_s * fb * fb;
#pragma unroll
        for (int k = 0; k < KB; k++) {
            float bk  = -5.f + 0.2f * (float)(BSTART + k);
            float ea = ex2(fmaf(a_s, bk * bk, fmaf(p1a, bk, p0a)));
            float eb = ex2(fmaf(a_s, bk * bk, fmaf(p1b, bk, p0b)));
            acc[k] += ea + eb;
        }
    }
#pragma unroll
    for (int k = 0; k < KB; k++) {
        acc[k] = wredsum(acc[k]);
        if (lane == 0) sh_out[k] = acc[k];
    }
}

// K0: block handles dims d and d+128. Block-local counting sort (labels are
// 16KB, L2-broadcast) + gather into g_Fs. No stats, no copy (measured-fastest
// configuration: ~2us total residual).
__global__ void __launch_bounds__(256) k_gp(const int* __restrict__ lab32,
                                            const float* __restrict__ feature) {
    __shared__ short sperm[NPIX];          // 8KB
    __shared__ int scnt[8][20];            // [warp][class] -> excl prefix
    __shared__ int stot[20];
    __shared__ int soff[20];
    int tid  = threadIdx.x;
    int w    = tid >> 5;
    int lane = tid & 31;

    // words [0,4096): in-bounds under both dtype views of the label buffer.
    int aw[16];
#pragma unroll
    for (int r = 0; r < 16; r++) aw[r] = lab32[tid + r * 256];
    // int64 labels (0..18): all odd words zero; odd words owned by odd tid.
    int any = 0;
    if (tid & 1) {
#pragma unroll
        for (int r = 0; r < 16; r++) any |= aw[r];
    }
    int is32 = __syncthreads_or(any);

    if (lane < 20) scnt[w][lane] = 0;
    __syncwarp();

    int cs[16], rs[16];
#pragma unroll
    for (int r = 0; r < 16; r++) {
        int n = tid + r * 256;
        int c = is32 ? aw[r] : lab32[2 * n];
        c = max(0, min(NCLS - 1, c));
        cs[r] = c;
        unsigned mask = __match_any_sync(0xffffffffu, c);
        int base = scnt[w][c];
        rs[r] = base + __popc(mask & ((1u << lane) - 1u));
        if (lane == (__ffs(mask) - 1)) scnt[w][c] = base + __popc(mask);
        __syncwarp();
    }
    __syncthreads();

    // cross-warp exclusive prefix per class
    if (tid < NCLS) {
        int run = 0;
#pragma unroll
        for (int w2 = 0; w2 < 8; w2++) {
            int t = scnt[w2][tid];
            scnt[w2][tid] = run;
            run += t;
        }
        stot[tid] = run;
    }
    __syncthreads();
    if (tid == 0) {
        int off = 0;
        for (int c = 0; c < NCLS; c++) { soff[c] = off; off += stot[c]; }
    }
    __syncthreads();

#pragma unroll
    for (int r = 0; r < 16; r++) {
        int c = cs[r];
        sperm[soff[c] + scnt[w][c] + rs[r]] = (short)(tid + r * 256);
    }

    if (blockIdx.x == 0) {
        if (tid < NCLS) { g_cnt[tid] = stot[tid]; g_off[tid] = soff[tid]; }
        if (tid == NCLS) g_off[NCLS] = NPIX;
        for (int i = tid; i < NCLS * 32; i += 256) g_clsum2[i] = 0.f;
        if (tid == 255) g_ticket = 0;
    }
    __syncthreads();

#pragma unroll 1
    for (int dd = 0; dd < 2; dd++) {
        int d = blockIdx.x + dd * 128;
        const float* __restrict__ src = feature + d * NPIX;
        float* __restrict__ dst = g_Fs + d * NPIX;
        for (int j = tid; j < NPIX; j += 256)
            dst[j] = src[sperm[j]];
    }
}

// K1: one warp per (c,d), static grid (no queue). Stats pass (warms L1) +
// split 2px-ILP KDE + epilogue + spread atomic + ticketed finalize + copy.
__global__ void __launch_bounds__(128, 9)
k_main(const float* __restrict__ feature, float* __restrict__ out, int nf) {
    __shared__ float sh[4][52];
    int wslot = threadIdx.x >> 5;
    int wtask = blockIdx.x * 4 + wslot;   // 0..4863
    int lane = threadIdx.x & 31;
    int c = wtask >> 8;
    int d = wtask & 255;
    int off = g_off[c];
    int cnt = g_off[c + 1] - off;
    const float LOG2E = 1.4426950408889634f;

    if (cnt > 0) {
        const float* __restrict__ fp = g_Fs + d * NPIX + off;

        // pass 1: mean/var (also warms L1 for the KDE passes)
        float s1 = 0.f, s2 = 0.f;
        for (int i = lane; i < cnt; i += 32) {
            float f = fp[i];
            s1 += f;
            s2 = fmaf(f, f, s2);
        }
        s1 = wredsum(s1);
        s2 = wredsum(s2);
        float cm  = (float)cnt;
        float miu = s1 / cm;
        float var = fmaxf(s2 / cm - miu * miu, 1e-12f);

        // vs = var/25 ; base-2 coef: -12.5*log2e/var
        float a_s = -12.5f * LOG2E / var;

        kde_pass<26, 0>(fp, cnt, lane, a_s, &sh[wslot][0]);
        kde_pass<25, 26>(fp, cnt, lane, a_s, &sh[wslot][26]);
        __syncwarp();

        // epilogue: lane k owns bins k and k+32
        bool hi = lane < (NBINS - 32);
        float sv0 = sh[wslot][lane];
        float sv1 = hi ? sh[wslot][lane + 32] : 0.f;
        float sumS = wredsum(sv0 + sv1);

        float at = -0.5f * LOG2E / var;
        float b0 = fmaf(0.2f, (float)lane, -5.f);
        float b1 = b0 + 6.4f;
        float d0 = b0 - miu, d1 = b1 - miu;
        float g0 = ex2(at * d0 * d0);
        float g1 = hi ? ex2(at * d1 * d1) : 0.f;
        float sumT = wredsum(g0 + g1);

        float invS = 1.f / fmaxf(sumS, 1e-30f);
        float invT = 1.f / fmaxf(sumT, 1e-30f);

        float df0 = sv0 * invS - g0 * invT;
        float df1 = sv1 * invS - g1 * invT;
        float ad0 = fabsf(df0), ad1 = fabsf(df1);
        float l0 = (ad0 < 1.f) ? 0.5f * df0 * df0 : ad0 - 0.5f;
        float l1 = (ad1 < 1.f) ? 0.5f * df1 * df1 : ad1 - 0.5f;
        if (!hi) l1 = 0.f;

        float sl = wredsum(l0 + l1);
        if (lane == 0) atomicAdd(&g_clsum2[c * 32 + (d & 31)], sl);
    }

    // publish, ticket; the last of the NW warps finalizes.
    __threadfence();
    int tk = 0;
    if (lane == 0) tk = atomicAdd(&g_ticket, 1);
    tk = __shfl_sync(0xffffffffu, tk, 0);
    if (tk == NW - 1) {
        float v = 0.f, a = 0.f;
#pragma unroll
        for (int j = 1; j < NCLS; j++) {          // class 0 excluded
            int cj = __ldcg(&g_cnt[j]);
            float x = __ldcg(&g_clsum2[j * 32 + lane]);
            if (cj > 0) { v += x; a += (lane == 0) ? 1.f : 0.f; }
        }
        v = wredsum(v);
        a = wredsum(a);
        if (lane == 0) out[0] = (v * (1.f / 13056.f)) / (a + 1e-12f);
    }

    // output copy: out[1..nf] = feature[0..nf), overlapped across blocks
    int gt = blockIdx.x * 128 + threadIdx.x;
    for (int j = gt; j < nf; j += NBLK * 128)
        out[1 + j] = feature[j];
}

extern "C" void kernel_launch(void* const* d_in, const int* in_sizes, int n_in,
                              void* d_out, int out_size) {
    // Inputs: feature (1048576 f32) and label (4096 px); smaller buffer = label.
    int fi = 0, li = 1;
    if (n_in >= 2 && in_sizes[0] < in_sizes[1]) { fi = 1; li = 0; }
    const float* feature = (const float*)d_in[fi];
    const int*   label   = (const int*)d_in[li];
    float* out = (float*)d_out;

    int nf = out_size - 1;
    int cap = DIM * NPIX;
    if (nf > cap) nf = cap;
    if (nf < 0) nf = 0;

    k_gp<<<128, 256>>>(label, feature);
    k_main<<<NBLK, 128>>>(feature, out, nf);
}